// round 6
// baseline (speedup 1.0000x reference)
#include <cuda_runtime.h>
#include <cstdint>

// CenterLoss collapses: mask is one-hot per row, clip() lifts masked-out zeros
// to exactly 1e-12:
//   loss = (1/B) * sum_b clamp(||x_b - c_{label_b}||^2, 1e-12, 1e12)
//          + (NUM_CLASSES - 1) * 1e-12
// R6: 256 blocks, each warp owns 2 consecutive samples with all 16 float4
// loads front-batched (per-thread MLP=16). Fewer blocks => smaller cross-CTA
// L1tex-queue spread and a 4x cheaper atomic/final-reduce tail.

#define CL_BATCH       4096
#define CL_DIM         512
#define CL_NUM_CLASSES 10000
#define CL_THREADS     256
#define CL_WARPS       8
#define CL_NBLOCKS     256   // 2048 warps, 2 samples per warp

__device__ float        g_cl_partials[CL_NBLOCKS];
__device__ unsigned int g_cl_count = 0;

// Labels may be int64 or int32. For int64 (values < 10000) every odd 32-bit
// word is the zero high-half; for int32 the odd words are random labels.
// 8 odd words all-zero => int64 (misclassification prob ~1e-32).
__device__ __forceinline__ int cl_load_label(const int* __restrict__ lw, int b) {
    int or_acc = 0;
#pragma unroll
    for (int i = 0; i < 8; ++i) or_acc |= lw[2 * i + 1];
    return (or_acc == 0) ? lw[2 * b] : lw[b];
}

__device__ __forceinline__ float cl_sq8(const float4 a0, const float4 a1,
                                        const float4 c0, const float4 c1) {
    float d, acc;
    d = a0.x - c0.x; acc = d * d;
    d = a0.y - c0.y; acc = fmaf(d, d, acc);
    d = a0.z - c0.z; acc = fmaf(d, d, acc);
    d = a0.w - c0.w; acc = fmaf(d, d, acc);
    d = a1.x - c1.x; acc = fmaf(d, d, acc);
    d = a1.y - c1.y; acc = fmaf(d, d, acc);
    d = a1.z - c1.z; acc = fmaf(d, d, acc);
    d = a1.w - c1.w; acc = fmaf(d, d, acc);
    return acc;
}

__global__ __launch_bounds__(CL_THREADS)
void centerloss_fused_kernel(const float* __restrict__ x,
                             const int* __restrict__ label_words,
                             const float* __restrict__ centers,
                             float* __restrict__ out) {
    const int warp = threadIdx.x >> 5;
    const int lane = threadIdx.x & 31;
    const int wg   = blockIdx.x * CL_WARPS + warp;   // 0..2047
    const int b0   = wg * 2;                          // consecutive samples
    const int b1   = b0 + 1;

    // Labels for both samples (lanes 0/1), overlapped with x loads below.
    int lbl = 0;
    if (lane < 2) lbl = cl_load_label(label_words, b0 + lane);
    const int lbl0 = __shfl_sync(0xffffffffu, lbl, 0);
    const int lbl1 = __shfl_sync(0xffffffffu, lbl, 1);

    const float4* __restrict__ xr0 =
        reinterpret_cast<const float4*>(x + (size_t)b0 * CL_DIM);
    const float4* __restrict__ xr1 =
        reinterpret_cast<const float4*>(x + (size_t)b1 * CL_DIM);
    const float4* __restrict__ cr0 =
        reinterpret_cast<const float4*>(centers + (size_t)lbl0 * CL_DIM);
    const float4* __restrict__ cr1 =
        reinterpret_cast<const float4*>(centers + (size_t)lbl1 * CL_DIM);

    // Front-batch all 16 float4 loads (x first: no label dependency).
    float4 a0[4], a1[4], c0[4], c1[4];
#pragma unroll
    for (int i = 0; i < 4; ++i) a0[i] = xr0[lane + i * 32];
#pragma unroll
    for (int i = 0; i < 4; ++i) a1[i] = xr1[lane + i * 32];
#pragma unroll
    for (int i = 0; i < 4; ++i) c0[i] = cr0[lane + i * 32];
#pragma unroll
    for (int i = 0; i < 4; ++i) c1[i] = cr1[lane + i * 32];

    float acc0 = cl_sq8(a0[0], a0[1], c0[0], c0[1])
               + cl_sq8(a0[2], a0[3], c0[2], c0[3]);
    float acc1 = cl_sq8(a1[0], a1[1], c1[0], c1[1])
               + cl_sq8(a1[2], a1[3], c1[2], c1[3]);

#pragma unroll
    for (int o = 16; o > 0; o >>= 1) {
        acc0 += __shfl_xor_sync(0xffffffffu, acc0, o);
        acc1 += __shfl_xor_sync(0xffffffffu, acc1, o);
    }

    __shared__ float s[CL_WARPS];
    if (lane == 0) {
        // clamp each sample like reference clip(dist, 1e-12, 1e12), then sum
        s[warp] = fminf(fmaxf(acc0, 1e-12f), 1e12f)
                + fminf(fmaxf(acc1, 1e-12f), 1e12f);
    }
    __syncthreads();

    __shared__ bool is_last;
    if (threadIdx.x == 0) {
        float t = 0.0f;
#pragma unroll
        for (int i = 0; i < CL_WARPS; ++i) t += s[i];
        g_cl_partials[blockIdx.x] = t;
        __threadfence();
        // atomicInc wraps old==NBLOCKS-1 -> 0: auto-reset for graph replay.
        unsigned int prev = atomicInc(&g_cl_count, CL_NBLOCKS - 1);
        is_last = (prev == CL_NBLOCKS - 1);
    }
    __syncthreads();

    // Last block reduces all 256 partials in double (fixed order).
    if (is_last) {
        __shared__ double sd[CL_THREADS];
        const int t = threadIdx.x;
        sd[t] = (double)g_cl_partials[t];
        __syncthreads();
#pragma unroll
        for (int stride = CL_THREADS / 2; stride > 32; stride >>= 1) {
            if (t < stride) sd[t] += sd[t + stride];
            __syncthreads();
        }
        if (t < 32) {
            double w = sd[t] + sd[t + 32];
#pragma unroll
            for (int o = 16; o > 0; o >>= 1)
                w += __shfl_xor_sync(0xffffffffu, w, o);
            if (t == 0) {
                const double zeros_term = (double)(CL_NUM_CLASSES - 1) * 1e-12;
                out[0] = (float)(w / (double)CL_BATCH + zeros_term);
            }
        }
    }
}

extern "C" void kernel_launch(void* const* d_in, const int* in_sizes, int n_in,
                              void* d_out, int out_size) {
    // Identify inputs by unique element counts:
    //   x: 4096*512 = 2097152, centers: 10000*512 = 5120000, labels: 4096.
    const float* x       = nullptr;
    const float* centers = nullptr;
    const int*   labels  = nullptr;
    for (int i = 0; i < n_in; ++i) {
        if (in_sizes[i] == CL_BATCH * CL_DIM)            x       = (const float*)d_in[i];
        else if (in_sizes[i] == CL_NUM_CLASSES * CL_DIM) centers = (const float*)d_in[i];
        else if (in_sizes[i] == CL_BATCH)                labels  = (const int*)d_in[i];
    }
    if (!x)       x       = (const float*)d_in[0];
    if (!labels)  labels  = (const int*)d_in[1];
    if (!centers) centers = (const float*)d_in[2];

    centerloss_fused_kernel<<<CL_NBLOCKS, CL_THREADS>>>(
        x, labels, centers, (float*)d_out);
}

// round 7
// speedup vs baseline: 1.0036x; 1.0036x over previous
#include <cuda_runtime.h>
#include <cstdint>

// CenterLoss collapses: mask is one-hot per row, clip() lifts masked-out zeros
// to exactly 1e-12:
//   loss = (1/B) * sum_b clamp(||x_b - c_{label_b}||^2, 1e-12, 1e12)
//          + (NUM_CLASSES - 1) * 1e-12
// R7: best-known config (512 blocks x 256 thr, warp-per-sample) with the tail
// collapsed: per-block double atomicAdd into one accumulator + wrap-counter
// election. Last block does no reduction (one read, one store, reset).

#define CL_BATCH       4096
#define CL_DIM         512
#define CL_NUM_CLASSES 10000
#define CL_WARPS       8                       // samples per block (1 warp each)
#define CL_THREADS     (CL_WARPS * 32)         // 256
#define CL_NBLOCKS     (CL_BATCH / CL_WARPS)   // 512

__device__ double       g_cl_accum = 0.0;
__device__ unsigned int g_cl_count = 0;

// Labels may be int64 or int32. For int64 (values < 10000) every odd 32-bit
// word is the zero high-half; for int32 the odd words are random labels.
// 8 odd words all-zero => int64 (misclassification prob ~1e-32).
__device__ __forceinline__ int cl_load_label(const int* __restrict__ lw, int b) {
    int or_acc = 0;
#pragma unroll
    for (int i = 0; i < 8; ++i) or_acc |= lw[2 * i + 1];
    return (or_acc == 0) ? lw[2 * b] : lw[b];
}

__global__ __launch_bounds__(CL_THREADS)
void centerloss_fused_kernel(const float* __restrict__ x,
                             const int* __restrict__ label_words,
                             const float* __restrict__ centers,
                             float* __restrict__ out) {
    const int warp = threadIdx.x >> 5;
    const int lane = threadIdx.x & 31;
    const int b = blockIdx.x * CL_WARPS + warp;

    int lbl = 0;
    if (lane == 0) lbl = cl_load_label(label_words, b);
    lbl = __shfl_sync(0xffffffffu, lbl, 0);

    const float4* __restrict__ xr =
        reinterpret_cast<const float4*>(x + (size_t)b * CL_DIM);
    const float4* __restrict__ cr =
        reinterpret_cast<const float4*>(centers + (size_t)lbl * CL_DIM);

    // One warp per sample: 512 floats -> 16 per lane -> 4x float4 per side.
    float acc = 0.0f;
#pragma unroll
    for (int i = 0; i < 4; ++i) {
        const float4 a = xr[lane + i * 32];
        const float4 c = cr[lane + i * 32];
        const float d0 = a.x - c.x;
        const float d1 = a.y - c.y;
        const float d2 = a.z - c.z;
        const float d3 = a.w - c.w;
        acc = fmaf(d0, d0, acc);
        acc = fmaf(d1, d1, acc);
        acc = fmaf(d2, d2, acc);
        acc = fmaf(d3, d3, acc);
    }

#pragma unroll
    for (int o = 16; o > 0; o >>= 1)
        acc += __shfl_xor_sync(0xffffffffu, acc, o);

    __shared__ float s[CL_WARPS];
    if (lane == 0) {
        // clamp exactly like the reference clip(dist, 1e-12, 1e12)
        s[warp] = fminf(fmaxf(acc, 1e-12f), 1e12f);
    }
    __syncthreads();

    // Block partial -> single double accumulator; wrap-counter election.
    if (threadIdx.x == 0) {
        float t = 0.0f;
#pragma unroll
        for (int i = 0; i < CL_WARPS; ++i) t += s[i];
        atomicAdd(&g_cl_accum, (double)t);
        __threadfence();
        // atomicInc wraps old==NBLOCKS-1 -> 0: auto-reset for graph replay.
        const unsigned int prev = atomicInc(&g_cl_count, CL_NBLOCKS - 1);
        if (prev == CL_NBLOCKS - 1) {
            // All 512 adds are globally visible (each was fenced before its inc).
            const double total = atomicAdd(&g_cl_accum, 0.0);   // coherent read
            const double zeros_term = (double)(CL_NUM_CLASSES - 1) * 1e-12;
            out[0] = (float)(total / (double)CL_BATCH + zeros_term);
            // Reset accumulator for the next graph replay (stream-ordered).
            atomicExch((unsigned long long*)&g_cl_accum, 0ull);
        }
    }
}

extern "C" void kernel_launch(void* const* d_in, const int* in_sizes, int n_in,
                              void* d_out, int out_size) {
    // Identify inputs by unique element counts:
    //   x: 4096*512 = 2097152, centers: 10000*512 = 5120000, labels: 4096.
    const float* x       = nullptr;
    const float* centers = nullptr;
    const int*   labels  = nullptr;
    for (int i = 0; i < n_in; ++i) {
        if (in_sizes[i] == CL_BATCH * CL_DIM)            x       = (const float*)d_in[i];
        else if (in_sizes[i] == CL_NUM_CLASSES * CL_DIM) centers = (const float*)d_in[i];
        else if (in_sizes[i] == CL_BATCH)                labels  = (const int*)d_in[i];
    }
    if (!x)       x       = (const float*)d_in[0];
    if (!labels)  labels  = (const int*)d_in[1];
    if (!centers) centers = (const float*)d_in[2];

    centerloss_fused_kernel<<<CL_NBLOCKS, CL_THREADS>>>(
        x, labels, centers, (float*)d_out);
}